// round 6
// baseline (speedup 1.0000x reference)
#include <cuda_runtime.h>

#define NTYPES 20
#define LMAXC  13
#define DV     64
#define NRES_MAX 2048
#define B_MAX    16

__constant__ int c_res_len[NTYPES] = {3,4,5,5,6,6,6,7,7,7,7,7,8,8,8,9,10,10,11,13};

__device__ int g_starts[NRES_MAX];     // atom start per residue
__device__ int g_rowstart[NRES_MAX];   // first output-row per residue

// ---------------------------------------------------------------------------
// Setup: two warp-shuffle scans only (no rowmap).
// ---------------------------------------------------------------------------
__device__ __forceinline__ int block_excl_scan_pair(int my, int tid, int* wsum) {
    const int lane = tid & 31, wid = tid >> 5;
    int s = my;
#pragma unroll
    for (int o = 1; o < 32; o <<= 1) {
        int n = __shfl_up_sync(~0u, s, o);
        if (lane >= o) s += n;
    }
    if (lane == 31) wsum[wid] = s;
    __syncthreads();
    if (wid == 0) {
        int t = wsum[lane];
#pragma unroll
        for (int o = 1; o < 32; o <<= 1) {
            int n = __shfl_up_sync(~0u, t, o);
            if (lane >= o) t += n;
        }
        wsum[lane] = t;
    }
    __syncthreads();
    int base = ((wid > 0) ? wsum[wid - 1] : 0) + (s - my);
    __syncthreads();
    return base;
}

__global__ void setup_kernel(const int* __restrict__ seq, int nres) {
    __shared__ int wsum[32];
    __shared__ int slen[NTYPES];
    const int tid = threadIdx.x;
    if (tid < NTYPES) slen[tid] = c_res_len[tid];
    __syncthreads();

    const int j0 = 2 * tid, j1 = 2 * tid + 1;
    const int l0 = (j0 < nres) ? slen[seq[j0]] : 0;
    const int l1 = (j1 < nres) ? slen[seq[j1]] : 0;

    const int base = block_excl_scan_pair(l0 + l1, tid, wsum);
    if (j0 < nres) g_starts[j0] = base;
    if (j1 < nres) g_starts[j1] = base + l0;

    const int r0 = (j0 < nres) ? l0 + 1 : 0;
    const int r1 = (j1 < nres) ? l1 + 1 : 0;
    const int rbase = block_excl_scan_pair(r0 + r1, tid, wsum);
    if (j0 < nres) g_rowstart[j0] = rbase;
    if (j1 < nres) g_rowstart[j1] = rbase + r0;
}

// ---------------------------------------------------------------------------
// Main kernel helpers
// ---------------------------------------------------------------------------
#define PACK_DUP(dst, w) \
    asm("mov.b64 %0, {%1, %2};" : "=l"(dst) : "r"(__float_as_uint(w)), "r"(__float_as_uint(w)))
#define FMA2(acc, x, y) \
    asm("fma.rn.f32x2 %0, %1, %2, %3;" : "=l"(acc) : "l"(x), "l"(y), "l"(acc))
#define ADD2(dst, x, y) \
    asm("add.rn.f32x2 %0, %1, %2;" : "=l"(dst) : "l"(x), "l"(y))
#define UNPACK2(lo, hi, src) \
    asm("mov.b64 {%0, %1}, %2;" : "=r"(lo), "=r"(hi) : "l"(src))
#define LDS_V2U64(x, y, addr) \
    asm volatile("ld.shared.v2.u64 {%0, %1}, [%2];" : "=l"(x), "=l"(y) : "r"(addr))
#define SLOT_BAR(id) \
    asm volatile("bar.sync %0, 64;" :: "r"(id) : "memory")

__device__ __forceinline__ unsigned smem_u32(const void* p) {
    unsigned r;
    asm("{ .reg .u64 t; cvta.to.shared.u64 t, %1; cvt.u32.u64 %0, t; }" : "=r"(r) : "l"(p));
    return r;
}

// stage layout: [buf 2][slot 4][192 floats], 16B aligned
template <int L>
__device__ __forceinline__ void batch_loop(
    int B, bool active, unsigned curDiff,
    const float* __restrict__ wr,
    float* __restrict__ stage,      // &stage[0][slot][0]
    int v, int barId,
    float4* __restrict__ r4, long ostride4)
{
    unsigned long long ww[L];
#pragma unroll
    for (int l = 0; l < L; ++l) {
        const float w = __ldg(wr + l);
        PACK_DUP(ww[l], w);
    }

    const bool writer = (v < 48);
    float* stw0 = stage + 3 * v;               // buf0 STS target
    const float4* str0 = reinterpret_cast<const float4*>(stage) + v;  // buf0 LDS target

#pragma unroll 2
    for (int b = 0; b < B; ++b) {
        unsigned long long aA = 0ull, aB = 0ull, cA = 0ull, cB = 0ull;
#pragma unroll
        for (int l = 0; l < L; ++l) {
            unsigned long long d01, d2p;
            LDS_V2U64(d01, d2p, curDiff + l * 16);
            if (l & 1) { FMA2(aB, ww[l], d01); FMA2(cB, ww[l], d2p); }
            else       { FMA2(aA, ww[l], d01); FMA2(cA, ww[l], d2p); }
        }
        unsigned long long a01, a2p;
        ADD2(a01, aA, aB);
        ADD2(a2p, cA, cB);
        unsigned lo, hi, lo2, hi2;
        UNPACK2(lo, hi, a01);
        UNPACK2(lo2, hi2, a2p);

        const int buf = b & 1;
        float* stw = stw0 + buf * (4 * 192);
        stw[0] = __uint_as_float(lo);
        stw[1] = __uint_as_float(hi);
        stw[2] = __uint_as_float(lo2);

        SLOT_BAR(barId);

        if (writer && active) {
            const float4 val = *(str0 + buf * (4 * 48));
            *r4 = val;
        }
        r4 += ostride4;
        curDiff += 224u;
    }
}

__global__ __launch_bounds__(256) void posmix_kernel(
    const float* __restrict__ pos_atm, const float* __restrict__ pos_amn,
    const float* __restrict__ W_amn,  const float* __restrict__ W_atm,
    const int* __restrict__ seq,
    int B, int nres, int atoms, int totrows, float* __restrict__ out)
{
    __shared__ float sdif[4 * B_MAX * 56];                   // 14336 B
    __shared__ __align__(16) float stage[2 * 4 * 192];       // 6144 B

    const int tid  = threadIdx.x;
    const int slot = tid >> 6;
    const int v    = tid & 63;
    const int row  = blockIdx.x * 4 + slot;
    const bool active = (row < totrows);
    const int rowc = active ? row : (totrows - 1);

    // binary search: largest i with g_rowstart[i] <= rowc  (warp-uniform)
    int lo = 0, hi = nres - 1;
    while (lo < hi) {
        const int mid = (lo + hi + 1) >> 1;
        if (g_rowstart[mid] <= rowc) lo = mid; else hi = mid - 1;
    }
    const int i     = lo;
    const int m     = rowc - g_rowstart[i];
    const int start = g_starts[i];
    const int t     = seq[i];
    const int L     = c_res_len[t];
    const bool is_amn = (m == L);

    // --- compute diffs for this slot's residue, all batches, into smem ---
    if (v < 3 * L) {
        const int l = v / 3;
        const int d = v - 3 * l;
        const float* paP = pos_atm + (size_t)start * 3 + v;
        const float* pnP = pos_amn + (size_t)i * 3 + d;
        float* sd = sdif + slot * (B_MAX * 56) + l * 4 + d;
        const long astr = (long)atoms * 3;
        const long nstr = (long)nres * 3;
#pragma unroll 4
        for (int b = 0; b < B; ++b)
            sd[b * 56] = paP[b * astr] - pnP[b * nstr];
    }

    // weight row for this (m, v)
    const float* wr = is_amn
        ? (W_amn + ((size_t)t * DV + v) * LMAXC)
        : (W_atm + (((size_t)t * LMAXC + m) * DV + v) * LMAXC);

    // coalesced output: float4 index of this row's 192-float segment + v
    size_t base4; long ostride4;
    if (is_amn) {
        base4    = (size_t)B * atoms * 48 + (size_t)i * 48;
        ostride4 = (long)nres * 48;
    } else {
        base4    = (size_t)(start + m) * 48;
        ostride4 = (long)atoms * 48;
    }
    float4* r4 = reinterpret_cast<float4*>(out) + base4 + (v < 48 ? v : 0);

    __syncthreads();

    const unsigned curDiff = smem_u32(sdif) + (unsigned)(slot * (B_MAX * 56)) * 4u;
    float* stg = stage + slot * 192;
    const int barId = slot + 1;

    switch (L) {
        case  3: batch_loop< 3>(B, active, curDiff, wr, stg, v, barId, r4, ostride4); break;
        case  4: batch_loop< 4>(B, active, curDiff, wr, stg, v, barId, r4, ostride4); break;
        case  5: batch_loop< 5>(B, active, curDiff, wr, stg, v, barId, r4, ostride4); break;
        case  6: batch_loop< 6>(B, active, curDiff, wr, stg, v, barId, r4, ostride4); break;
        case  7: batch_loop< 7>(B, active, curDiff, wr, stg, v, barId, r4, ostride4); break;
        case  8: batch_loop< 8>(B, active, curDiff, wr, stg, v, barId, r4, ostride4); break;
        case  9: batch_loop< 9>(B, active, curDiff, wr, stg, v, barId, r4, ostride4); break;
        case 10: batch_loop<10>(B, active, curDiff, wr, stg, v, barId, r4, ostride4); break;
        case 11: batch_loop<11>(B, active, curDiff, wr, stg, v, barId, r4, ostride4); break;
        default: batch_loop<13>(B, active, curDiff, wr, stg, v, barId, r4, ostride4); break;
    }
}

// ---------------------------------------------------------------------------
extern "C" void kernel_launch(void* const* d_in, const int* in_sizes, int n_in,
                              void* d_out, int out_size) {
    const float* pos_atm = (const float*)d_in[0];
    const float* pos_amn = (const float*)d_in[1];
    const float* W_amn   = (const float*)d_in[2];
    const float* W_atm   = (const float*)d_in[3];
    const int*   seq     = (const int*)d_in[4];

    const int nres  = in_sizes[4];
    const int B     = in_sizes[1] / (nres * 3);
    const int atoms = in_sizes[0] / (B * 3);
    const int totrows = atoms + nres;       // sum over residues of (L+1)

    setup_kernel<<<1, 1024>>>(seq, nres);
    const int nblocks = (totrows + 3) / 4;
    posmix_kernel<<<nblocks, 256>>>(pos_atm, pos_amn, W_amn, W_atm, seq,
                                    B, nres, atoms, totrows, (float*)d_out);
}